// round 5
// baseline (speedup 1.0000x reference)
#include <cuda_runtime.h>
#include <cstdint>

// HMM forward filter, one warp per batch. Normalization AND rescaling are both
// off the recurrence chain:
//   t  = v ∘ lik_k                      (chain head, 4 cyc)
//   v' = (t @ T) · f_prev               (chain: STS/sync/LDS + fma2 + one mul2)
//   s  = Σt ; r = 1/s                   (shadow: shfl butterfly + rcp)
//   f_prev<- 2^(127-exp(s))             (shadow; consumed NEXT step — exact pow2)
//   est_out = t·r ; pred_out = (t@T)·r  (shadow STGs)
// Valid because est/pred are scale-invariant ratios of v, and T row-stochastic
// means sum(t@T)=sum(t) so s doubles as pred's normalizer.
// Lane p owns states (2p,2p+1); T columns in regs as {T[j][2p],T[j][2p+1]};
// t exchanged as duplicated pairs {t,t}; all matvec LDS are lane-invariant
// (crossbar broadcast). lik prefetched via 8-deep register FIFO.

#define Bn 256
#define Hn 2048
#define Sn 64
#define UD 8

using u64 = unsigned long long;

__device__ __forceinline__ u64 fma2(u64 a, u64 b, u64 c) {
    u64 d; asm("fma.rn.f32x2 %0, %1, %2, %3;" : "=l"(d) : "l"(a), "l"(b), "l"(c)); return d;
}
__device__ __forceinline__ u64 mul2(u64 a, u64 b) {
    u64 d; asm("mul.rn.f32x2 %0, %1, %2;" : "=l"(d) : "l"(a), "l"(b)); return d;
}
__device__ __forceinline__ u64 add2(u64 a, u64 b) {
    u64 d; asm("add.rn.f32x2 %0, %1, %2;" : "=l"(d) : "l"(a), "l"(b)); return d;
}
__device__ __forceinline__ u64 pack2(float lo, float hi) {
    u64 d; asm("mov.b64 %0, {%1, %2};" : "=l"(d) : "f"(lo), "f"(hi)); return d;
}
__device__ __forceinline__ void unpack2(u64 a, float& x, float& y) {
    asm("mov.b64 {%0, %1}, %2;" : "=f"(x), "=f"(y) : "l"(a));
}
__device__ __forceinline__ float fast_rcp(float s) {
    float r; asm("rcp.approx.f32 %0, %1;" : "=f"(r) : "f"(s)); return r;
}

__global__ void __launch_bounds__(64, 1) hmm_forward_kernel(
    const float* __restrict__ lik,    // [B, H, S]
    const float* __restrict__ init_s, // [S]
    const float* __restrict__ Tm,     // [S, S] row-major
    float* __restrict__ est_out,      // [B, H, S]
    float* __restrict__ pred_out)     // [B, H, S]
{
    __shared__ alignas(16) u64 tdup[2][2][Sn];   // [warp][parity][state] = {t,t}

    const int p  = threadIdx.x & 31;
    const int lb = threadIdx.x >> 5;
    const int b  = blockIdx.x * 2 + lb;

    u64 TT[Sn];
#pragma unroll
    for (int j = 0; j < Sn; j++)
        TT[j] = *reinterpret_cast<const u64*>(Tm + j * Sn + 2 * p);

    const float* likp = lik + (size_t)b * Hn * Sn + 2 * p;
    float* eo = est_out  + (size_t)b * Hn * Sn + 2 * p;
    float* po = pred_out + (size_t)b * Hn * Sn + 2 * p;

    // ---- v = pred0 = init @ T ----
    {
        float a0 = init_s[2 * p], a1 = init_s[2 * p + 1];
        float4 f4; f4.x = a0; f4.y = a0; f4.z = a1; f4.w = a1;
        *reinterpret_cast<float4*>(&tdup[lb][1][2 * p]) = f4;
    }
    __syncwarp();
    u64 v2;
    {
        const ulonglong2* uv = reinterpret_cast<const ulonglong2*>(tdup[lb][1]);
        u64 a0 = 0, a1 = 0, a2 = 0, a3 = 0;
#pragma unroll
        for (int t = 0; t < 32; t += 2) {
            ulonglong2 w0 = uv[t];
            ulonglong2 w1 = uv[t + 1];
            a0 = fma2(w0.x, TT[2 * t + 0], a0);
            a1 = fma2(w0.y, TT[2 * t + 1], a1);
            a2 = fma2(w1.x, TT[2 * t + 2], a2);
            a3 = fma2(w1.y, TT[2 * t + 3], a3);
        }
        v2 = add2(add2(a0, a1), add2(a2, a3));
    }
    __syncwarp();

    u64 fifo[UD];
#pragma unroll
    for (int j = 0; j < UD; j++)
        fifo[j] = *reinterpret_cast<const u64*>(likp + (size_t)j * Sn);

    float f_prev = 1.0f;   // pred0 sums to exactly 1 (init prob vec, T stochastic)

    for (int kk = 0; kk < Hn; kk += UD) {
#pragma unroll
        for (int j = 0; j < UD; j++) {
            const int k = kk + j;
            const u64 lk = fifo[j];
            int kn = k + UD; if (kn > Hn - 1) kn = Hn - 1;
            fifo[j] = *reinterpret_cast<const u64*>(likp + (size_t)kn * Sn);

            // ---- chain: t = v ∘ lik, exchange as dup pairs ----
            const u64 t2 = mul2(v2, lk);
            float tx, ty; unpack2(t2, tx, ty);
            u64* tb = tdup[lb][k & 1];
            { float4 f4; f4.x = tx; f4.y = tx; f4.z = ty; f4.w = ty;
              *reinterpret_cast<float4*>(&tb[2 * p]) = f4; }
            __syncwarp();

            // ---- shadow: s = Σt, r, and NEXT step's rescale factor ----
            float s = fabsf(tx) + fabsf(ty);
#pragma unroll
            for (int o = 16; o; o >>= 1) s += __shfl_xor_sync(0xFFFFFFFFu, s, o);
            s = fmaxf(s, 1e-35f);
            const float r = fast_rcp(s);
            const unsigned eb = (__float_as_uint(s) >> 23) & 0xFFu;
            const float f_new = __uint_as_float((254u - eb) << 23);   // 2^(127-e)

            // ---- chain: v' = (t @ T) · f_prev ----
            u64 a0 = 0, a1 = 0, a2 = 0, a3 = 0, a4 = 0, a5 = 0, a6 = 0, a7 = 0;
            const ulonglong2* uv = reinterpret_cast<const ulonglong2*>(tb);
#pragma unroll
            for (int t = 0; t < 32; t += 4) {
                ulonglong2 w0 = uv[t];
                ulonglong2 w1 = uv[t + 1];
                ulonglong2 w2 = uv[t + 2];
                ulonglong2 w3 = uv[t + 3];
                a0 = fma2(w0.x, TT[2 * t + 0], a0);
                a1 = fma2(w0.y, TT[2 * t + 1], a1);
                a2 = fma2(w1.x, TT[2 * t + 2], a2);
                a3 = fma2(w1.y, TT[2 * t + 3], a3);
                a4 = fma2(w2.x, TT[2 * t + 4], a4);
                a5 = fma2(w2.y, TT[2 * t + 5], a5);
                a6 = fma2(w3.x, TT[2 * t + 6], a6);
                a7 = fma2(w3.y, TT[2 * t + 7], a7);
            }
            const u64 sum = add2(add2(add2(a0, a1), add2(a2, a3)),
                                 add2(add2(a4, a5), add2(a6, a7)));

            v2 = mul2(sum, pack2(f_prev, f_prev));   // only off-chain scalar on chain
            f_prev = f_new;

            // ---- shadow: normalized outputs ----
            const u64 rr = pack2(r, r);
            *reinterpret_cast<u64*>(eo + (size_t)k * Sn) = mul2(t2, rr);
            *reinterpret_cast<u64*>(po + (size_t)k * Sn) = mul2(sum, rr);
        }
    }
}

extern "C" void kernel_launch(void* const* d_in, const int* in_sizes, int n_in,
                              void* d_out, int out_size) {
    const float* lik    = (const float*)d_in[0];   // [256, 2048, 64]
    const float* init_s = (const float*)d_in[1];   // [64]
    const float* Tm     = (const float*)d_in[2];   // [64, 64]
    float* eo = (float*)d_out;                      // est_traj first
    float* po = eo + (size_t)Bn * Hn * Sn;          // pred_traj second

    hmm_forward_kernel<<<Bn / 2, 64>>>(lik, init_s, Tm, eo, po);
}

// round 7
// speedup vs baseline: 1.2978x; 1.2978x over previous
#include <cuda_runtime.h>
#include <cstdint>

// HMM forward filter — TWO warps per batch (output-split), norm fully shadowed.
// Warp q of a batch owns states i in [32q, 32q+32); lane p carries scalar v_i,
// i = 32q+p. Per step:
//   chain:  t_i = v_i * lik_i ; STS t_i ; bar(batch) ; 16x LDS.128 of t pairs ;
//           32x fma2 with TTp[m]={T[2m][i],T[2m+1][i]} ; tree+horiz add -> out_i ;
//           v_i = out_i * f_scale (pow2, from s_total(k-1))
//   shadow: warp-half sum via shfl butterfly -> smem ; step-(k-1) outputs written
//           with exact r_{k-1} = 1/s_total(k-1) (one-step output lag)
// T row-stochastic => sum(t@T)=sum(t), so one sum serves est and pred norms.
// lik prefetched via 8-deep register FIFO. grid=128 x block=128 (2 batches,
// 4 warps -> one warp per SMSP).

#define Bn 256
#define Hn 2048
#define Sn 64
#define UD 8

using u64 = unsigned long long;

__device__ __forceinline__ u64 fma2(u64 a, u64 b, u64 c) {
    u64 d; asm("fma.rn.f32x2 %0, %1, %2, %3;" : "=l"(d) : "l"(a), "l"(b), "l"(c)); return d;
}
__device__ __forceinline__ u64 add2(u64 a, u64 b) {
    u64 d; asm("add.rn.f32x2 %0, %1, %2;" : "=l"(d) : "l"(a), "l"(b)); return d;
}
__device__ __forceinline__ u64 pack2(float lo, float hi) {
    u64 d; asm("mov.b64 %0, {%1, %2};" : "=l"(d) : "f"(lo), "f"(hi)); return d;
}
__device__ __forceinline__ void unpack2(u64 a, float& x, float& y) {
    asm("mov.b64 {%0, %1}, %2;" : "=f"(x), "=f"(y) : "l"(a));
}
__device__ __forceinline__ float fast_rcp(float s) {
    float r; asm("rcp.approx.f32 %0, %1;" : "=f"(r) : "f"(s)); return r;
}
__device__ __forceinline__ void bar_batch(int id) {
    asm volatile("bar.sync %0, 64;" :: "r"(id) : "memory");
}

__global__ void __launch_bounds__(128, 1) hmm_forward_kernel(
    const float* __restrict__ lik,    // [B, H, S]
    const float* __restrict__ init_s, // [S]
    const float* __restrict__ Tm,     // [S, S] row-major
    float* __restrict__ est_out,      // [B, H, S]
    float* __restrict__ pred_out)     // [B, H, S]
{
    __shared__ alignas(16) float tbuf[2][2][Sn];  // [batch][parity][state]
    __shared__ float ssum[2][2][2];               // [batch][parity][warp-half]

    const int tid = threadIdx.x;
    const int lb  = tid >> 6;          // local batch 0/1
    const int bt  = tid & 63;
    const int q   = bt >> 5;           // output half
    const int p   = bt & 31;
    const int i   = 32 * q + p;        // owned state
    const int b   = blockIdx.x * 2 + lb;
    const int barid = 1 + lb;

    // T column i as input pairs: TTp[m] = {T[2m][i], T[2m+1][i]}
    u64 TTp[32];
#pragma unroll
    for (int m = 0; m < 32; m++)
        TTp[m] = pack2(Tm[(2 * m) * Sn + i], Tm[(2 * m + 1) * Sn + i]);

    const float* likp = lik + (size_t)b * Hn * Sn + i;
    float* eo = est_out  + (size_t)b * Hn * Sn + i;
    float* po = pred_out + (size_t)b * Hn * Sn + i;

    // ---- v = pred0 = init @ T (stage init in parity-1 buffer) ----
    tbuf[lb][1][i] = init_s[i];
    bar_batch(barid);
    float v;
    {
        const ulonglong2* tv = reinterpret_cast<const ulonglong2*>(tbuf[lb][1]);
        u64 a0 = 0, a1 = 0;
#pragma unroll
        for (int t = 0; t < 16; t++) {
            ulonglong2 w = tv[t];
            a0 = fma2(w.x, TTp[2 * t + 0], a0);
            a1 = fma2(w.y, TTp[2 * t + 1], a1);
        }
        u64 s2 = add2(a0, a1);
        float sx, sy; unpack2(s2, sx, sy);
        v = sx + sy;
    }

    // ---- lik FIFO ----
    float fifo[UD];
#pragma unroll
    for (int j = 0; j < UD; j++)
        fifo[j] = likp[(size_t)j * Sn];

    float f_scale = 1.0f;      // pred0 sums to exactly 1
    float t_prev = 0.f, out_prev = 0.f, s_my = 0.f;

    for (int kk = 0; kk < Hn; kk += UD) {
#pragma unroll
        for (int j = 0; j < UD; j++) {
            const int k = kk + j;
            const float lk = fifo[j];
            int kn = k + UD; if (kn > Hn - 1) kn = Hn - 1;
            fifo[j] = likp[(size_t)kn * Sn];

            // ---- chain head: t_i = v_i * lik, publish ----
            const float t = v * lk;
            tbuf[lb][k & 1][i] = t;
            bar_batch(barid);

            // ---- shadow: finish step k-1 (exact r from global sum) ----
            if (k > 0) {
                float s_tot = s_my + ssum[lb][(k - 1) & 1][1 - q];
                s_tot = fmaxf(s_tot, 1e-35f);
                const float r = fast_rcp(s_tot);
                eo[(size_t)(k - 1) * Sn] = t_prev * r;
                po[(size_t)(k - 1) * Sn] = out_prev * r;
                const unsigned eb = (__float_as_uint(s_tot) >> 23) & 0xFFu;
                f_scale = __uint_as_float((254u - eb) << 23);  // exact 2^(127-e)
            }

            // ---- chain: out_i = sum_j t_j T[j][i] ----
            u64 a0 = 0, a1 = 0, a2 = 0, a3 = 0, a4 = 0, a5 = 0, a6 = 0, a7 = 0;
            const ulonglong2* tv = reinterpret_cast<const ulonglong2*>(tbuf[lb][k & 1]);
#pragma unroll
            for (int t4 = 0; t4 < 16; t4 += 4) {
                ulonglong2 w0 = tv[t4 + 0];
                ulonglong2 w1 = tv[t4 + 1];
                ulonglong2 w2 = tv[t4 + 2];
                ulonglong2 w3 = tv[t4 + 3];
                a0 = fma2(w0.x, TTp[2 * t4 + 0], a0);
                a1 = fma2(w0.y, TTp[2 * t4 + 1], a1);
                a2 = fma2(w1.x, TTp[2 * t4 + 2], a2);
                a3 = fma2(w1.y, TTp[2 * t4 + 3], a3);
                a4 = fma2(w2.x, TTp[2 * t4 + 4], a4);
                a5 = fma2(w2.y, TTp[2 * t4 + 5], a5);
                a6 = fma2(w3.x, TTp[2 * t4 + 6], a6);
                a7 = fma2(w3.y, TTp[2 * t4 + 7], a7);
            }
            const u64 s2 = add2(add2(add2(a0, a1), add2(a2, a3)),
                                add2(add2(a4, a5), add2(a6, a7)));
            float sx, sy; unpack2(s2, sx, sy);
            const float out = sx + sy;

            // chain tail: pow2 rescale (factor from shadow, one step lagged)
            v = out * f_scale;

            // ---- shadow: my half-sum for step k ----
            float sm = t;
#pragma unroll
            for (int o = 16; o; o >>= 1) sm += __shfl_xor_sync(0xFFFFFFFFu, sm, o);
            if (p == 0) ssum[lb][k & 1][q] = sm;
            s_my = sm;
            t_prev = t;
            out_prev = out;
        }
    }

    // ---- flush last step's outputs ----
    bar_batch(barid);
    {
        float s_tot = s_my + ssum[lb][(Hn - 1) & 1][1 - q];
        s_tot = fmaxf(s_tot, 1e-35f);
        const float r = fast_rcp(s_tot);
        eo[(size_t)(Hn - 1) * Sn] = t_prev * r;
        po[(size_t)(Hn - 1) * Sn] = out_prev * r;
    }
}

extern "C" void kernel_launch(void* const* d_in, const int* in_sizes, int n_in,
                              void* d_out, int out_size) {
    const float* lik    = (const float*)d_in[0];   // [256, 2048, 64]
    const float* init_s = (const float*)d_in[1];   // [64]
    const float* Tm     = (const float*)d_in[2];   // [64, 64]
    float* eo = (float*)d_out;                      // est_traj first
    float* po = eo + (size_t)Bn * Hn * Sn;          // pred_traj second

    hmm_forward_kernel<<<Bn / 2, 128>>>(lik, init_s, Tm, eo, po);
}